// round 1
// baseline (speedup 1.0000x reference)
#include <cuda_runtime.h>
#include <cuda_bf16.h>
#include <cstdint>

// CFConv fused kernel, fp32 SIMT with packed f32x2 FMA (sm_103a).
// h[dst] += node_weight[src] * ( ssp(rbf @ W1 + b1) @ W2 + b2 )

typedef unsigned long long ull;

__device__ __forceinline__ ull pack2(float a, float b) {
    ull r;
    asm("mov.b64 %0, {%1,%2};" : "=l"(r) : "f"(a), "f"(b));
    return r;
}
__device__ __forceinline__ void unpack2(ull v, float& a, float& b) {
    asm("mov.b64 {%0,%1}, %2;" : "=f"(a), "=f"(b) : "l"(v));
}
__device__ __forceinline__ ull ffma2(ull a, ull b, ull c) {
    ull d;
    asm("fma.rn.f32x2 %0, %1, %2, %3;" : "=l"(d) : "l"(a), "l"(b), "l"(c));
    return d;
}

// shifted softplus matching reference: half=0.5x; half>14 ? x : 2*log(1+exp(half))
__device__ __forceinline__ float ssp(float x) {
    float h = 0.5f * x;
    return (h > 14.0f) ? x : 2.0f * __logf(1.0f + __expf(h));
}

// Shared-memory layout (floats):
//  W1S  [64*64]      @ 0
//  W2S  [64*64]      @ 4096
//  B1S  [64]         @ 8192
//  B2S  [64]         @ 8256
//  RBFS [128*68]     @ 8320   (row stride 68 floats, 16B aligned, conflict-free)
//  HIDS [128*68]     @ 17024
static constexpr int SMEM_FLOATS = 17024 + 128 * 68;     // 25728
static constexpr int SMEM_BYTES  = SMEM_FLOATS * 4;      // 102912

// One 64x64 GEMM tile: acc[ii][p] (f32x2 pairs) += S[i][k] * W[k][d]
// thread owns edges i = ty + 16*ii (ii=0..7), dims d = tx*4..tx*4+3 and tx*4+32..+35
__device__ __forceinline__ void gemm_tile(const float* __restrict__ S,
                                          const float* __restrict__ WS,
                                          ull acc[8][4], int ty, int dx4) {
    for (int k0 = 0; k0 < 64; k0 += 4) {
        float4 rv[8];
#pragma unroll
        for (int ii = 0; ii < 8; ii++)
            rv[ii] = *(const float4*)&S[(ty + 16 * ii) * 68 + k0];
#pragma unroll
        for (int kk = 0; kk < 4; kk++) {
            const ulonglong2 wa = *(const ulonglong2*)&WS[(k0 + kk) * 64 + dx4];
            const ulonglong2 wb = *(const ulonglong2*)&WS[(k0 + kk) * 64 + dx4 + 32];
#pragma unroll
            for (int ii = 0; ii < 8; ii++) {
                float v = (kk == 0) ? rv[ii].x : (kk == 1) ? rv[ii].y
                        : (kk == 2) ? rv[ii].z : rv[ii].w;
                ull vv = pack2(v, v);
                acc[ii][0] = ffma2(vv, wa.x, acc[ii][0]);
                acc[ii][1] = ffma2(vv, wa.y, acc[ii][1]);
                acc[ii][2] = ffma2(vv, wb.x, acc[ii][2]);
                acc[ii][3] = ffma2(vv, wb.y, acc[ii][3]);
            }
        }
    }
}

__global__ void __launch_bounds__(128, 2)
cfconv_kernel(const float* __restrict__ nw,   // [N,64]
              const float* __restrict__ rbf,  // [E,64]
              const float* __restrict__ W1,   // [64,64] (in,out)
              const float* __restrict__ b1,   // [64]
              const float* __restrict__ W2,   // [64,64]
              const float* __restrict__ b2,   // [64]
              const int*   __restrict__ src,  // [E]
              const int*   __restrict__ dst,  // [E]
              float* __restrict__ out,        // [N,64]
              int E) {
    extern __shared__ float sm[];
    float* W1S  = sm;
    float* W2S  = sm + 4096;
    float* B1S  = sm + 8192;
    float* B2S  = sm + 8256;
    float* RBFS = sm + 8320;
    float* HIDS = sm + 17024;

    const int tid = threadIdx.x;

    // Load weights / biases once per block (L2-hot after first block)
    for (int i = tid; i < 1024; i += 128) {
        ((float4*)W1S)[i] = ((const float4*)W1)[i];
        ((float4*)W2S)[i] = ((const float4*)W2)[i];
    }
    if (tid < 64) { B1S[tid] = b1[tid]; B2S[tid] = b2[tid]; }
    __syncthreads();

    const int tx  = tid & 7;     // 8 d-groups
    const int ty  = tid >> 3;    // 16 i-groups
    const int dx4 = tx * 4;

    // bias packs (constant across tiles)
    ull b1p[4], b2p[4];
    b1p[0] = pack2(B1S[dx4],      B1S[dx4 + 1]);
    b1p[1] = pack2(B1S[dx4 + 2],  B1S[dx4 + 3]);
    b1p[2] = pack2(B1S[dx4 + 32], B1S[dx4 + 33]);
    b1p[3] = pack2(B1S[dx4 + 34], B1S[dx4 + 35]);
    b2p[0] = pack2(B2S[dx4],      B2S[dx4 + 1]);
    b2p[1] = pack2(B2S[dx4 + 2],  B2S[dx4 + 3]);
    b2p[2] = pack2(B2S[dx4 + 32], B2S[dx4 + 33]);
    b2p[3] = pack2(B2S[dx4 + 34], B2S[dx4 + 35]);

    const int ntiles = (E + 127) >> 7;
    for (int t = blockIdx.x; t < ntiles; t += gridDim.x) {
        const int et = t << 7;

        // Stage rbf tile [128 x 64] -> shared (stride 68), zero-fill tail
        for (int i = tid; i < 2048; i += 128) {
            int row = i >> 4;
            int c4  = (i & 15) * 4;
            float4 v = make_float4(0.f, 0.f, 0.f, 0.f);
            int e = et + row;
            if (e < E) v = *(const float4*)&rbf[(long)e * 64 + c4];
            *(float4*)&RBFS[row * 68 + c4] = v;
        }
        __syncthreads();

        // ---- GEMM1: hidden = ssp(rbf @ W1 + b1) ----
        ull acc[8][4];
#pragma unroll
        for (int ii = 0; ii < 8; ii++)
#pragma unroll
            for (int p = 0; p < 4; p++) acc[ii][p] = b1p[p];

        gemm_tile(RBFS, W1S, acc, ty, dx4);

#pragma unroll
        for (int ii = 0; ii < 8; ii++) {
            float a0, a1, a2, a3, a4, a5, a6, a7;
            unpack2(acc[ii][0], a0, a1);
            unpack2(acc[ii][1], a2, a3);
            unpack2(acc[ii][2], a4, a5);
            unpack2(acc[ii][3], a6, a7);
            float4 h1 = make_float4(ssp(a0), ssp(a1), ssp(a2), ssp(a3));
            float4 h2 = make_float4(ssp(a4), ssp(a5), ssp(a6), ssp(a7));
            int row = ty + 16 * ii;
            *(float4*)&HIDS[row * 68 + dx4]      = h1;
            *(float4*)&HIDS[row * 68 + dx4 + 32] = h2;
        }
        __syncthreads();

        // ---- GEMM2: e = hidden @ W2 + b2 ----
#pragma unroll
        for (int ii = 0; ii < 8; ii++)
#pragma unroll
            for (int p = 0; p < 4; p++) acc[ii][p] = b2p[p];

        gemm_tile(HIDS, W2S, acc, ty, dx4);

        // ---- Epilogue: m = nw[src]*e ; atomic scatter to out[dst] ----
#pragma unroll
        for (int ii = 0; ii < 8; ii++) {
            int e = et + ty + 16 * ii;
            if (e < E) {
                int s = src[e];
                int d = dst[e];
                float4 na = *(const float4*)&nw[(long)s * 64 + dx4];
                float4 nb = *(const float4*)&nw[(long)s * 64 + dx4 + 32];
                float a0, a1, a2, a3, a4, a5, a6, a7;
                unpack2(acc[ii][0], a0, a1);
                unpack2(acc[ii][1], a2, a3);
                unpack2(acc[ii][2], a4, a5);
                unpack2(acc[ii][3], a6, a7);
                float* ob = out + (long)d * 64;
                atomicAdd(ob + dx4 + 0,  a0 * na.x);
                atomicAdd(ob + dx4 + 1,  a1 * na.y);
                atomicAdd(ob + dx4 + 2,  a2 * na.z);
                atomicAdd(ob + dx4 + 3,  a3 * na.w);
                atomicAdd(ob + dx4 + 32, a4 * nb.x);
                atomicAdd(ob + dx4 + 33, a5 * nb.y);
                atomicAdd(ob + dx4 + 34, a6 * nb.z);
                atomicAdd(ob + dx4 + 35, a7 * nb.w);
            }
        }
        // NOTE: no trailing sync needed — next iteration's RBFS staging only
        // races with this iteration's GEMM2 (reads HIDS, not RBFS); the sync
        // after staging orders everything else.
    }
}

__global__ void zero_kernel(float4* __restrict__ o, int n4) {
    int i = blockIdx.x * blockDim.x + threadIdx.x;
    if (i < n4) o[i] = make_float4(0.f, 0.f, 0.f, 0.f);
}

extern "C" void kernel_launch(void* const* d_in, const int* in_sizes, int n_in,
                              void* d_out, int out_size) {
    const float* nw  = (const float*)d_in[0];
    const float* rbf = (const float*)d_in[1];
    const float* W1  = (const float*)d_in[2];
    const float* b1  = (const float*)d_in[3];
    const float* W2  = (const float*)d_in[4];
    const float* b2  = (const float*)d_in[5];
    const int*   src = (const int*)d_in[6];
    const int*   dst = (const int*)d_in[7];
    float* out = (float*)d_out;

    const int E = in_sizes[1] / 64;

    cudaFuncSetAttribute(cfconv_kernel,
                         cudaFuncAttributeMaxDynamicSharedMemorySize, SMEM_BYTES);

    int n4 = out_size / 4;
    zero_kernel<<<(n4 + 255) / 256, 256>>>((float4*)out, n4);

    cfconv_kernel<<<296, 128, SMEM_BYTES>>>(nw, rbf, W1, b1, W2, b2, src, dst, out, E);
}

// round 4
// speedup vs baseline: 1.9691x; 1.9691x over previous
#include <cuda_runtime.h>
#include <cuda_bf16.h>
#include <cstdint>

// CFConv fused via mma.sync tf32 (works on plain sm_103 target; tcgen05 is
// sm_103a-only and this build assembles for sm_103).
// out[dst] += nw[src] * ( ssp(rbf @ W1 + b1) @ W2 + b2 )

static constexpr int TILE    = 128;   // edges per tile
static constexpr int THREADS = 128;   // 4 warps
static constexpr int STRIDE  = 68;    // floats per row in shared tile (conflict-free)

// shared layout (floats)
static constexpr int SBUF_OFF = 0;                 // 128 x 68 tile (reused 3x)
static constexpr int W1F_OFF  = TILE * STRIDE;     // 8704: W1 fragments, 4096 floats
static constexpr int W2F_OFF  = W1F_OFF + 4096;    // 12800
static constexpr int B1_OFF   = W2F_OFF + 4096;    // 16896
static constexpr int B2_OFF   = B1_OFF + 64;       // 16960
static constexpr int SMEM_FLOATS = B2_OFF + 64;    // 17024
static constexpr int SMEM_BYTES  = SMEM_FLOATS * 4; // 68096

__device__ __forceinline__ float to_tf32(float x) {
    float r;
    asm("cvt.rna.tf32.f32 %0, %1;" : "=f"(r) : "f"(x));
    return r;
}

__device__ __forceinline__ void mma8(float c[4], const uint32_t a[4], const uint32_t b[2]) {
    asm volatile(
        "mma.sync.aligned.m16n8k8.row.col.f32.tf32.tf32.f32 "
        "{%0,%1,%2,%3}, {%4,%5,%6,%7}, {%8,%9}, {%0,%1,%2,%3};"
        : "+f"(c[0]), "+f"(c[1]), "+f"(c[2]), "+f"(c[3])
        : "r"(a[0]), "r"(a[1]), "r"(a[2]), "r"(a[3]), "r"(b[0]), "r"(b[1]));
}

__device__ __forceinline__ float ssp(float x) {
    float h = 0.5f * x;
    if (h > 14.0f) return x;
    return 2.0f * __logf(1.0f + __expf(h));
}

__device__ __forceinline__ void red4(float* p, float a, float b, float c, float d) {
    asm volatile("red.global.add.v4.f32 [%0], {%1,%2,%3,%4};"
                 :: "l"(p), "f"(a), "f"(b), "f"(c), "f"(d) : "memory");
}

__device__ __forceinline__ void cp16(const float* s, const void* g) {
    uint32_t sa;
    asm("{.reg .u64 t; cvta.to.shared.u64 t, %1; cvt.u32.u64 %0, t;}" : "=r"(sa) : "l"(s));
    asm volatile("cp.async.cg.shared.global [%0], [%1], 16;" :: "r"(sa), "l"(g));
}

// One 64-col GEMM: acc[mt][j][4] += tile(S, rows warp*32..+32) @ Wfrag.
// Fragment layout (m16n8k8): a0=(r,c) a1=(r+8,c) a2=(r,c+4) a3=(r+8,c+4),
// r = lane/4, c = lane%4; B pre-packed so each thread lds.64's its {b0,b1}.
__device__ __forceinline__ void gemm64(const float* __restrict__ S,
                                       const float* __restrict__ WF,
                                       float acc[2][8][4], int warp, int lane) {
    const int r = lane >> 2, c = lane & 3;
#pragma unroll
    for (int s = 0; s < 8; s++) {
        uint32_t a[2][4];
#pragma unroll
        for (int mt = 0; mt < 2; mt++) {
            const float* base = S + (warp * 32 + mt * 16 + r) * STRIDE + s * 8 + c;
            a[mt][0] = __float_as_uint(to_tf32(base[0]));
            a[mt][1] = __float_as_uint(to_tf32(base[8 * STRIDE]));
            a[mt][2] = __float_as_uint(to_tf32(base[4]));
            a[mt][3] = __float_as_uint(to_tf32(base[8 * STRIDE + 4]));
        }
#pragma unroll
        for (int j = 0; j < 8; j++) {
            uint2 bv = *(const uint2*)&WF[((s * 8 + j) * 32 + lane) * 2];
            uint32_t b[2] = {bv.x, bv.y};
            mma8(acc[0][j], a[0], b);
            mma8(acc[1][j], a[1], b);
        }
    }
}

__global__ void __launch_bounds__(THREADS, 3)
cfconv_kernel(const float* __restrict__ nw,
              const float* __restrict__ rbf,
              const float* __restrict__ W1,
              const float* __restrict__ b1,
              const float* __restrict__ W2,
              const float* __restrict__ b2,
              const int*   __restrict__ src,
              const int*   __restrict__ dst,
              float* __restrict__ out,
              int E) {
    extern __shared__ __align__(16) float sm[];
    float* SBUF = sm + SBUF_OFF;
    float* W1F  = sm + W1F_OFF;
    float* W2F  = sm + W2F_OFF;
    float* B1S  = sm + B1_OFF;
    float* B2S  = sm + B2_OFF;

    const int tid  = threadIdx.x;
    const int warp = tid >> 5;
    const int lane = tid & 31;
    const int r = lane >> 2, c = lane & 3;

    // ---- one-time: pack weights into per-thread fragment order (tf32) ----
    // frag f: s=f/512, j=(f%512)/64, t=(f%64)/2, h=f%2 ; k=s*8+(t&3)+h*4, n=j*8+t/4
    for (int f = tid; f < 4096; f += THREADS) {
        int s = f >> 9, j = (f >> 6) & 7, t = (f >> 1) & 31, h = f & 1;
        int k = s * 8 + (t & 3) + h * 4;
        int n = j * 8 + (t >> 2);
        W1F[f] = to_tf32(W1[k * 64 + n]);
        W2F[f] = to_tf32(W2[k * 64 + n]);
    }
    if (tid < 64) { B1S[tid] = b1[tid]; B2S[tid] = b2[tid]; }
    __syncthreads();

    const int ntiles = (E + TILE - 1) / TILE;

    for (int t = blockIdx.x; t < ntiles; t += gridDim.x) {
        const int et = t * TILE;

        // ---- stage rbf tile [128 x 64] -> SBUF (stride 68) ----
#pragma unroll
        for (int i = 0; i < 16; i++) {
            int g = tid + i * THREADS;       // float4 index
            int row = g >> 4, q = g & 15;
            int e = et + row;
            float* d = &SBUF[row * STRIDE + q * 4];
            if (e < E) cp16(d, rbf + (long)e * 64 + q * 4);
            else       *(float4*)d = make_float4(0.f, 0.f, 0.f, 0.f);
        }
        asm volatile("cp.async.commit_group;" ::: "memory");
        asm volatile("cp.async.wait_group 0;" ::: "memory");
        __syncthreads();

        // ---- GEMM1 ----
        float acc[2][8][4];
#pragma unroll
        for (int mt = 0; mt < 2; mt++)
#pragma unroll
            for (int j = 0; j < 8; j++)
#pragma unroll
                for (int p = 0; p < 4; p++) acc[mt][j][p] = 0.f;
        gemm64(SBUF, W1F, acc, warp, lane);
        __syncthreads();   // all warps done reading rbf tile

        // ---- hidden = ssp(acc + b1) -> SBUF (overwrite) ----
#pragma unroll
        for (int mt = 0; mt < 2; mt++) {
            int row0 = warp * 32 + mt * 16 + r;
#pragma unroll
            for (int j = 0; j < 8; j++) {
                int col = j * 8 + 2 * c;
                float2 bb = *(float2*)&B1S[col];
                float2 h0 = make_float2(ssp(acc[mt][j][0] + bb.x), ssp(acc[mt][j][1] + bb.y));
                float2 h1 = make_float2(ssp(acc[mt][j][2] + bb.x), ssp(acc[mt][j][3] + bb.y));
                *(float2*)&SBUF[row0 * STRIDE + col]       = h0;
                *(float2*)&SBUF[(row0 + 8) * STRIDE + col] = h1;
            }
        }
        __syncthreads();

        // ---- GEMM2 ----
#pragma unroll
        for (int mt = 0; mt < 2; mt++)
#pragma unroll
            for (int j = 0; j < 8; j++)
#pragma unroll
                for (int p = 0; p < 4; p++) acc[mt][j][p] = 0.f;
        gemm64(SBUF, W2F, acc, warp, lane);
        __syncthreads();   // all warps done reading hidden

        // ---- filter = acc + b2 -> SBUF (overwrite) ----
#pragma unroll
        for (int mt = 0; mt < 2; mt++) {
            int row0 = warp * 32 + mt * 16 + r;
#pragma unroll
            for (int j = 0; j < 8; j++) {
                int col = j * 8 + 2 * c;
                float2 bb = *(float2*)&B2S[col];
                *(float2*)&SBUF[row0 * STRIDE + col] =
                    make_float2(acc[mt][j][0] + bb.x, acc[mt][j][1] + bb.y);
                *(float2*)&SBUF[(row0 + 8) * STRIDE + col] =
                    make_float2(acc[mt][j][2] + bb.x, acc[mt][j][3] + bb.y);
            }
        }
        __syncthreads();

        // ---- epilogue: thread owns one edge row ----
        const int e = et + tid;
        if (e < E) {
            const int sN = src[e];
            const int dN = dst[e];
            const float4* nr = (const float4*)(nw + (long)sN * 64);
            float* ob = out + (long)dN * 64;
            const float* rw = &SBUF[tid * STRIDE];
#pragma unroll
            for (int q = 0; q < 16; q++) {
                float4 cv = *(const float4*)&rw[q * 4];
                float4 nv = nr[q];
                red4(ob + q * 4, cv.x * nv.x, cv.y * nv.y, cv.z * nv.z, cv.w * nv.w);
            }
        }
        __syncthreads();   // protect SBUF before next tile's staging
    }
}

__global__ void zero_kernel(float4* __restrict__ o, int n4) {
    int i = blockIdx.x * blockDim.x + threadIdx.x;
    if (i < n4) o[i] = make_float4(0.f, 0.f, 0.f, 0.f);
}

extern "C" void kernel_launch(void* const* d_in, const int* in_sizes, int n_in,
                              void* d_out, int out_size) {
    const float* nw  = (const float*)d_in[0];
    const float* rbf = (const float*)d_in[1];
    const float* W1  = (const float*)d_in[2];
    const float* b1  = (const float*)d_in[3];
    const float* W2  = (const float*)d_in[4];
    const float* b2  = (const float*)d_in[5];
    const int*   src = (const int*)d_in[6];
    const int*   dst = (const int*)d_in[7];
    float* out = (float*)d_out;

    const int E = in_sizes[1] / 64;

    cudaFuncSetAttribute(cfconv_kernel,
                         cudaFuncAttributeMaxDynamicSharedMemorySize, SMEM_BYTES);

    int n4 = out_size / 4;
    zero_kernel<<<(n4 + 255) / 256, 256>>>((float4*)out, n4);

    cfconv_kernel<<<444, THREADS, SMEM_BYTES>>>(nw, rbf, W1, b1, W2, b2, src, dst, out, E);
}